// round 17
// baseline (speedup 1.0000x reference)
#include <cuda_runtime.h>

#define BATCH 32
#define HH 1024
#define WW 1024
#define HS 64                         // emit rows per block
#define NSTRIP (HH / HS)              // 16
#define RS4 (WW / 4)                  // 256 float4 per row
#define NBLK (NSTRIP * BATCH)         // 512 blocks

// Deterministic per-block partials + completion ticket (self-resetting).
__device__ double g_bceP[NSTRIP][BATCH];
__device__ double g_intP[NSTRIP][BATCH];
__device__ double g_uniP[NSTRIP][BATCH];
__device__ unsigned int g_ticket;     // zero-init; last block resets to 0

// Fused per-pixel math (vs = 31x31 box SUM).
// bce-term == x*(1-t) + ln(1+e^{-x}); sigmoid via MUFU.TANH;
// ln(1+e^{-x}) = -ln2*lg2(sigmoid(x)).
__device__ __forceinline__ void px(float xv, float tv, float vs,
                                   float& bceA, float& intA, float& uniA) {
    const float avg  = vs * (1.0f / 961.0f);
    const float weit = fmaf(5.0f, fabsf(avg - tv), 1.0f);
    float th;
    asm("tanh.approx.f32 %0, %1;" : "=f"(th) : "f"(xv * 0.5f));
    const float p = fmaf(0.5f, th, 0.5f);             // sigmoid(x)
    float lg;
    asm("lg2.approx.f32 %0, %1;" : "=f"(lg) : "f"(p));
    bceA = fmaf(-0.6931471805599453f, lg, bceA);      // += ln(1+e^{-x})
    bceA += fmaf(-xv, tv, xv);                        // += x*(1-t)
    intA = fmaf(p * tv, weit, intA);
    uniA = fmaf(p + tv, weit, uniA);
}

// Full-row fused kernel: 128 threads x 8 columns (2 float4 chunks) per thread.
// Loop overhead, barrier, publish, and window interior amortize over 8 px;
// group B's horizontal window slides from group A's. 2x MLP per warp.
__global__ void __launch_bounds__(128, 4)
fused_kernel(const float4* __restrict__ inp, const float4* __restrict__ tgt,
             float* __restrict__ out, int n) {
    __shared__ float4 win[2][264];              // [buf][4 guard | 256 | 4 guard]
    __shared__ float  Ssum[2][264];             // scalar chunk sums, same layout
    __shared__ float red[3][4];
    __shared__ bool isLast;

    const int tid  = threadIdx.x;               // 0..127
    const int lane = tid & 31;
    const int w    = tid >> 5;                  // warp 0..3
    const int c0   = 2 * tid;                   // first owned float4 chunk 0..254
    const int y0   = blockIdx.x * HS;           // strip
    const int b    = blockIdx.y;                // batch
    const size_t img = (size_t)b * HH * RS4;
    const float4* T = tgt + img;
    const float4* X = inp + img;

    const float4 z4 = make_float4(0.f, 0.f, 0.f, 0.f);

    // zero guard entries of both buffers once (indices 0..3 and 260..263)
    if (tid < 4) {
        win[0][tid] = z4;        win[1][tid] = z4;
        Ssum[0][tid] = 0.f;      Ssum[1][tid] = 0.f;
        win[0][260 + tid] = z4;  win[1][260 + tid] = z4;
        Ssum[0][260 + tid] = 0.f; Ssum[1][260 + tid] = 0.f;
    }

    // ---- warm-up: vertical window sums for output row y0 (rows y0-15..y0+15)
    float4 V0 = z4, V1 = z4;
    {
        const int wbeg = (y0 - 15 < 0) ? 0 : y0 - 15;
        const int wend = (y0 + 15 > HH - 1) ? HH - 1 : y0 + 15;
        for (int yy = wbeg; yy <= wend; ++yy) {
            const float4 a0 = T[yy * RS4 + c0];
            const float4 a1 = T[yy * RS4 + c0 + 1];
            V0.x += a0.x; V0.y += a0.y; V0.z += a0.z; V0.w += a0.w;
            V1.x += a1.x; V1.y += a1.y; V1.z += a1.z; V1.w += a1.w;
        }
    }

    float bceA = 0.f, intA = 0.f, uniA = 0.f;

    for (int j = 0; j < HS; ++j) {
        const int y  = y0 + j;
        const int yl = y + 16, yr = y - 15;
        // gmem: leading tgt rows (DRAM), re-reads (L2), streamed inp — 8 LDG batched
        float4 lead0 = z4, lead1 = z4, rem0 = z4, rem1 = z4;
        if (yl < HH) { lead0 = T[yl * RS4 + c0]; lead1 = T[yl * RS4 + c0 + 1]; }
        if (yr >= 0) { rem0  = T[yr * RS4 + c0]; rem1  = T[yr * RS4 + c0 + 1]; }
        const float4 tv0 = T[y * RS4 + c0];
        const float4 tv1 = T[y * RS4 + c0 + 1];
        const float4 xv0 = __ldcs(&X[y * RS4 + c0]);
        const float4 xv1 = __ldcs(&X[y * RS4 + c0 + 1]);

        // ---- publish both chunks + scalar sums (double-buffered, 1 barrier)
        const int buf = j & 1;
        win[buf][4 + c0]     = V0;
        win[buf][5 + c0]     = V1;
        Ssum[buf][4 + c0]    = (V0.x + V0.y) + (V0.z + V0.w);
        Ssum[buf][5 + c0]    = (V1.x + V1.y) + (V1.z + V1.w);
        __syncthreads();

        // ---- horizontal 31-tap sums for 8 px; group B slides from group A
        const float4 FA0 = win[buf][c0];          // chunk c0-4
        const float4 FA8 = win[buf][c0 + 8];      // chunk c0+4
        const float4 FB0 = win[buf][c0 + 1];      // chunk c0-3
        const float4 FB8 = win[buf][c0 + 9];      // chunk c0+5
        float midA = Ssum[buf][c0 + 1];
        #pragma unroll
        for (int k = 2; k <= 7; ++k) midA += Ssum[buf][c0 + k];
        const float midB = midA - Ssum[buf][c0 + 1] + Ssum[buf][c0 + 8];

        const float hA0 = midA + FA0.y + FA0.z + FA0.w;
        const float hA1 = hA0 + FA8.x - FA0.y;
        const float hA2 = hA1 + FA8.y - FA0.z;
        const float hA3 = hA2 + FA8.z - FA0.w;
        const float hB0 = midB + FB0.y + FB0.z + FB0.w;
        const float hB1 = hB0 + FB8.x - FB0.y;
        const float hB2 = hB1 + FB8.y - FB0.z;
        const float hB3 = hB2 + FB8.z - FB0.w;

        px(xv0.x, tv0.x, hA0, bceA, intA, uniA);
        px(xv0.y, tv0.y, hA1, bceA, intA, uniA);
        px(xv0.z, tv0.z, hA2, bceA, intA, uniA);
        px(xv0.w, tv0.w, hA3, bceA, intA, uniA);
        px(xv1.x, tv1.x, hB0, bceA, intA, uniA);
        px(xv1.y, tv1.y, hB1, bceA, intA, uniA);
        px(xv1.z, tv1.z, hB2, bceA, intA, uniA);
        px(xv1.w, tv1.w, hB3, bceA, intA, uniA);

        // slide vertical windows y -> y+1 (exact fp32 cancellation)
        V0.x += lead0.x - rem0.x; V0.y += lead0.y - rem0.y;
        V0.z += lead0.z - rem0.z; V0.w += lead0.w - rem0.w;
        V1.x += lead1.x - rem1.x; V1.y += lead1.y - rem1.y;
        V1.z += lead1.z - rem1.z; V1.w += lead1.w - rem1.w;
    }

    // ---- block reduction -> deterministic partial slot
    #pragma unroll
    for (int o = 16; o > 0; o >>= 1) {
        bceA += __shfl_down_sync(0xffffffffu, bceA, o);
        intA += __shfl_down_sync(0xffffffffu, intA, o);
        uniA += __shfl_down_sync(0xffffffffu, uniA, o);
    }
    if (lane == 0) { red[0][w] = bceA; red[1][w] = intA; red[2][w] = uniA; }
    __syncthreads();
    if (tid == 0) {
        double rb = 0, ri = 0, ru = 0;
        #pragma unroll
        for (int k = 0; k < 4; ++k) { rb += red[0][k]; ri += red[1][k]; ru += red[2][k]; }
        g_bceP[blockIdx.x][b] = rb;
        g_intP[blockIdx.x][b] = ri;
        g_uniP[blockIdx.x][b] = ru;
        __threadfence();
        const unsigned t = atomicAdd(&g_ticket, 1u);
        isLast = (t == NBLK - 1);
    }
    __syncthreads();

    // ---- fused finalize: exactly one block runs this (deterministic math)
    if (isLast && tid < 32) {
        const int bb = tid;                    // one batch per lane
        double sb = 0, si = 0, su = 0;
        #pragma unroll
        for (int s = 0; s < NSTRIP; ++s) {
            sb += g_bceP[s][bb]; si += g_intP[s][bb]; su += g_uniP[s][bb];
        }
        double tb = sb;
        #pragma unroll
        for (int o = 16; o > 0; o >>= 1) tb += __shfl_down_sync(0xffffffffu, tb, o);
        double wiou = 1.0 - (si + 1.0) / (su - si + 1.0);
        #pragma unroll
        for (int o = 16; o > 0; o >>= 1) wiou += __shfl_down_sync(0xffffffffu, wiou, o);
        if (bb == 0) {
            const double bce = tb / (double)((size_t)BATCH * HH * WW);
            // wbce == bce exactly (scalar factors out of the weighted mean)
            const float r = (float)(bce + wiou / (double)BATCH);
            for (int i = 0; i < n; ++i) out[i] = r;
            g_ticket = 0;                      // reset for next graph replay
        }
    }
}

extern "C" void kernel_launch(void* const* d_in, const int* in_sizes, int n_in,
                              void* d_out, int out_size) {
    const float* inp = (const float*)d_in[0];   // "input"
    const float* tgt = (const float*)d_in[1];   // "target"
    float* out = (float*)d_out;

    fused_kernel<<<dim3(NSTRIP, BATCH), 128>>>(
        (const float4*)inp, (const float4*)tgt, out, out_size);
}